// round 16
// baseline (speedup 1.0000x reference)
#include <cuda_runtime.h>
#include <cstdint>

#define BB 512
#define TT 256
#define CC 128
#define HH 128
#define BTH ((size_t)BB * TT * HH)

// scratch for q projection: holds tf32 BITS of q*scale (written by proj)
static __device__ float g_q[BTH];

// ============================ helpers ======================================
__device__ __forceinline__ uint32_t f2tf32(float f) {
    uint32_t r;
    asm("cvt.rna.tf32.f32 %0, %1;" : "=r"(r) : "f"(f));
    return r;
}

// m16n8k8 tf32 mma, fp32 accumulate (portable mma.sync — works on compute_103)
__device__ __forceinline__ void mma_tf32(float* c, const uint32_t* a, const uint32_t* b) {
    asm volatile(
        "mma.sync.aligned.m16n8k8.row.col.f32.tf32.tf32.f32 "
        "{%0,%1,%2,%3}, {%4,%5,%6,%7}, {%8,%9}, {%0,%1,%2,%3};"
        : "+f"(c[0]), "+f"(c[1]), "+f"(c[2]), "+f"(c[3])
        : "r"(a[0]), "r"(a[1]), "r"(a[2]), "r"(a[3]), "r"(b[0]), "r"(b[1]));
}

#define SCALE 0.08838834764831845f  // 128^-0.5 (n_embd scaling)

// ---------------------------------------------------------------------------
// Kernel 1: QKV projection, one (64-row tile, matrix) pair per CTA.
// Grid: (2048, 3) CTAs x 256 threads (8 warps). blockIdx.y = matrix.
// x-load and W-load issue concurrently before the first sync; short chain:
// load -> sync -> mma -> sync -> stage -> sync -> store.
// smem: xs 64x136 + ws 128x136 = 104,448 B -> 2 CTAs/SM.
// ---------------------------------------------------------------------------
#define PSTR 136
#define PROJ_SMEM ((64 * PSTR + 128 * PSTR) * 4)

__global__ void __launch_bounds__(256, 2) proj_kernel(
    const float* __restrict__ x,
    const float* __restrict__ Wk,
    const float* __restrict__ Wq,
    const float* __restrict__ Wv,
    float* __restrict__ out)
{
    extern __shared__ uint32_t usm[];
    uint32_t* xs = usm;              // 64 x 136 (tf32 bits / fp32 staging)
    uint32_t* ws = usm + 64 * PSTR;  // 128 x 136 (tf32 bits)

    const int t    = threadIdx.x;
    const int warp = t >> 5;
    const int lane = t & 31;
    const int g  = lane >> 2;
    const int tq = lane & 3;
    const int m  = blockIdx.y;                  // matrix: 0=k, 1=q, 2=v
    const size_t row0 = (size_t)blockIdx.x * 64;

    const float* W = (m == 0) ? Wk : (m == 1) ? Wq : Wv;
    float* dst = (m == 0) ? out + BTH + row0 * HH
               : (m == 1) ? g_q + row0 * HH
                          : out + 2 * BTH + row0 * HH;

    // load x tile [64 x 128] and W [128 x 128] -> smem (tf32), concurrently
    {
        const float4* xg = (const float4*)(x + row0 * CC);
        for (int i = t; i < 64 * 32; i += 256) {
            int r = i >> 5, c = (i & 31) * 4;
            float4 v = xg[i];
            uint32_t* d = &xs[r * PSTR + c];
            d[0] = f2tf32(v.x); d[1] = f2tf32(v.y);
            d[2] = f2tf32(v.z); d[3] = f2tf32(v.w);
        }
        const float4* Wg = (const float4*)W;
        for (int i = t; i < 128 * 32; i += 256) {
            int kr = i >> 5, n = (i & 31) * 4;
            float4 v = Wg[i];
            uint32_t* d = &ws[kr * PSTR + n];
            d[0] = f2tf32(v.x); d[1] = f2tf32(v.y);
            d[2] = f2tf32(v.z); d[3] = f2tf32(v.w);
        }
    }
    __syncthreads();

    // warp tile: rows mb=(warp&1)*32, cols nb=(warp>>1)*32
    const int mb = (warp & 1) * 32;
    const int nb = (warp >> 1) * 32;

    float acc[2][4][4];
#pragma unroll
    for (int mi = 0; mi < 2; mi++)
#pragma unroll
        for (int ni = 0; ni < 4; ni++)
#pragma unroll
            for (int j = 0; j < 4; j++) acc[mi][ni][j] = 0.f;

#pragma unroll 4
    for (int k0 = 0; k0 < 16; k0++) {
        const int k = k0 * 8;
        uint32_t a[2][4], b[4][2];
#pragma unroll
        for (int mi = 0; mi < 2; mi++) {
            int r = mb + mi * 16 + g;
            a[mi][0] = xs[r * PSTR + k + tq];
            a[mi][1] = xs[(r + 8) * PSTR + k + tq];
            a[mi][2] = xs[r * PSTR + k + tq + 4];
            a[mi][3] = xs[(r + 8) * PSTR + k + tq + 4];
        }
#pragma unroll
        for (int ni = 0; ni < 4; ni++) {
            int col = nb + ni * 8 + g;
            b[ni][0] = ws[(k + tq) * PSTR + col];
            b[ni][1] = ws[(k + tq + 4) * PSTR + col];
        }
#pragma unroll
        for (int mi = 0; mi < 2; mi++)
#pragma unroll
            for (int ni = 0; ni < 4; ni++)
                mma_tf32(acc[mi][ni], a[mi], b[ni]);
    }

    __syncthreads();   // mma reads of xs done -> reuse xs as staging
    float* stg = (float*)xs;
#pragma unroll
    for (int mi = 0; mi < 2; mi++) {
#pragma unroll
        for (int ni = 0; ni < 4; ni++) {
            int r = mb + mi * 16 + g;
            int c = nb + ni * 8 + 2 * tq;
            float2 lo = {acc[mi][ni][0], acc[mi][ni][1]};
            float2 hi = {acc[mi][ni][2], acc[mi][ni][3]};
            *(float2*)&stg[r * PSTR + c] = lo;
            *(float2*)&stg[(r + 8) * PSTR + c] = hi;
        }
    }
    __syncthreads();

    if (m == 1) {
        // q: fold SCALE, convert to tf32 bits
        uint32_t* dq = (uint32_t*)dst;
        for (int i = t; i < 64 * 32; i += 256) {
            int r = i >> 5, c = (i & 31) * 4;
            float4 v = *(float4*)&stg[r * PSTR + c];
            uint4 w = {f2tf32(v.x * SCALE), f2tf32(v.y * SCALE),
                       f2tf32(v.z * SCALE), f2tf32(v.w * SCALE)};
            *(uint4*)&dq[(size_t)r * HH + c] = w;
        }
    } else {
        for (int i = t; i < 64 * 32; i += 256) {
            int r = i >> 5, c = (i & 31) * 4;
            *(float4*)&dst[(size_t)r * HH + c] = *(float4*)&stg[r * PSTR + c];
        }
    }
}

// ---------------------------------------------------------------------------
// Kernel 2: causal flash attention, tensor-pipe GEMMs, K/V overlaid in one
// smem buffer -> 87.8 KB -> 2 CTAs/SM. V global load overlapped with softmax.
// Grid: (4 q-blocks, 512 batches) x 256 threads (8 warps).
// (byte-identical to R13 — measured 174 us, occ 24.1%, tensor 20.4%)
// ---------------------------------------------------------------------------
#define AQ 136   // q/kv smem stride (words); 136%32==8 -> conflict-free frags
#define ASS 68   // S stride; 68%32==4
#define ATTN_SMEM ((2 * 64 * AQ + 64 * ASS + 3 * 64) * 4)

__global__ void __launch_bounds__(256, 2) attn_kernel(float* __restrict__ dout)
{
    extern __shared__ uint32_t usm[];
    uint32_t* qs  = usm;               // 64 x 136 tf32 bits (pre-scaled)
    uint32_t* kvs = qs + 64 * AQ;      // 64 x 136 tf32 bits (K, then V)
    float* S   = (float*)(kvs + 64 * AQ);  // 64 x 68 (scores / P tf32 bits)
    float* m_s = S + 64 * ASS;
    float* l_s = m_s + 64;
    float* f_s = l_s + 64;

    const int t    = threadIdx.x;
    const int warp = t >> 5;
    const int lane = t & 31;
    const int g  = lane >> 2;
    const int tq = lane & 3;
    const int qb = blockIdx.x;
    const int b  = blockIdx.y;
    const int qr0 = qb * 64;

    const uint32_t* qg = (const uint32_t*)g_q + ((size_t)b * TT + qr0) * HH;
    const float* kg = dout + BTH + (size_t)b * TT * HH;
    const float* vg = dout + 2 * BTH + (size_t)b * TT * HH;

    // load q tile (already tf32 bits)
    for (int i = t; i < 64 * 32; i += 256) {
        int r = i >> 5, c4 = i & 31;
        *(uint4*)&qs[r * AQ + c4 * 4] = ((const uint4*)qg)[i];
    }
    if (t < 64) { m_s[t] = -1e30f; l_s[t] = 0.f; }

    // S^T warp tiling: keys m = (warp&3)*16, queries n = (warp>>2)*32
    const int mK = (warp & 3) * 16;
    const int nQ = (warp >> 2) * 32;
    // PV warp tiling: queries m = (warp&1)*32, head n = (warp>>1)*32
    const int mQ = (warp & 1) * 32;
    const int nH = (warp >> 1) * 32;

    float oacc[2][4][4];
#pragma unroll
    for (int mt = 0; mt < 2; mt++)
#pragma unroll
        for (int ni = 0; ni < 4; ni++)
#pragma unroll
            for (int j = 0; j < 4; j++) oacc[mt][ni][j] = 0.f;

    for (int kt = 0; kt <= qb; kt++) {
        __syncthreads();   // prior Phase C reads of kvs (V) done
        // load K tile -> kvs
        {
            const float4* kgt = (const float4*)(kg + (size_t)kt * 64 * HH);
            for (int i = t; i < 64 * 32; i += 256) {
                int r = i >> 5, c4 = i & 31;
                float4 kv = kgt[i];
                uint4 kw = {f2tf32(kv.x), f2tf32(kv.y), f2tf32(kv.z), f2tf32(kv.w)};
                *(uint4*)&kvs[r * AQ + c4 * 4] = kw;
            }
        }
        __syncthreads();

        // ---- Phase A: S^T = K @ Q^T  (M=64 keys, N=64 queries, K=128)
        {
            float sacc[4][4];
#pragma unroll
            for (int ni = 0; ni < 4; ni++)
#pragma unroll
                for (int j = 0; j < 4; j++) sacc[ni][j] = 0.f;

#pragma unroll 4
            for (int k0 = 0; k0 < 16; k0++) {
                const int k = k0 * 8;
                uint32_t a[4];
                a[0] = kvs[(mK + g) * AQ + k + tq];
                a[1] = kvs[(mK + g + 8) * AQ + k + tq];
                a[2] = kvs[(mK + g) * AQ + k + tq + 4];
                a[3] = kvs[(mK + g + 8) * AQ + k + tq + 4];
#pragma unroll
                for (int ni = 0; ni < 4; ni++) {
                    int col = nQ + ni * 8 + g;
                    uint32_t bf[2] = {qs[col * AQ + k + tq], qs[col * AQ + k + tq + 4]};
                    mma_tf32(sacc[ni], a, bf);
                }
            }

            // store fragments transposed -> S[query][key], causal mask on diag
            const bool diag = (kt == qb);
#pragma unroll
            for (int ni = 0; ni < 4; ni++) {
                int colq = nQ + ni * 8 + 2 * tq;
#pragma unroll
                for (int j = 0; j < 4; j++) {
                    int key = mK + g + ((j >> 1) * 8);
                    int qi  = colq + (j & 1);
                    float sv = sacc[ni][j];
                    if (diag && key > qi) sv = -1e30f;
                    S[qi * ASS + key] = sv;
                }
            }
        }
        __syncthreads();   // A's reads of kvs(K) + writes of S done

        // ---- V global load (into regs, hidden behind softmax) ----
        float4 vreg[8];
        {
            const float4* vgt = (const float4*)(vg + (size_t)kt * 64 * HH);
#pragma unroll
            for (int j = 0; j < 8; j++)
                vreg[j] = vgt[t + 256 * j];
        }

        // ---- Phase B: online softmax (4 threads/row); P stored as tf32 bits
        {
            const int rB = t >> 2;
            const int cbB = (t & 3) * 16;
            float tm = -1e30f;
#pragma unroll
            for (int i = 0; i < 16; i++)
                tm = fmaxf(tm, S[rB * ASS + cbB + i]);
            tm = fmaxf(tm, __shfl_xor_sync(0xFFFFFFFFu, tm, 1));
            tm = fmaxf(tm, __shfl_xor_sync(0xFFFFFFFFu, tm, 2));

            float mo = m_s[rB];
            float nm = fmaxf(mo, tm);
            float ps = 0.f;
#pragma unroll
            for (int i = 0; i < 16; i++) {
                float p = __expf(S[rB * ASS + cbB + i] - nm);
                S[rB * ASS + cbB + i] = __uint_as_float(f2tf32(p));
                ps += p;
            }
            ps += __shfl_xor_sync(0xFFFFFFFFu, ps, 1);
            ps += __shfl_xor_sync(0xFFFFFFFFu, ps, 2);

            if ((t & 3) == 0) {
                float f = __expf(mo - nm);
                l_s[rB] = l_s[rB] * f + ps;
                m_s[rB] = nm;
                f_s[rB] = f;
            }
        }

        // ---- store V into kvs (K no longer needed) ----
#pragma unroll
        for (int j = 0; j < 8; j++) {
            int i = t + 256 * j;
            int r = i >> 5, c4 = i & 31;
            uint4 vw = {f2tf32(vreg[j].x), f2tf32(vreg[j].y),
                        f2tf32(vreg[j].z), f2tf32(vreg[j].w)};
            *(uint4*)&kvs[r * AQ + c4 * 4] = vw;
        }
        __syncthreads();   // V staged + softmax done

        // ---- Phase C: O = O*f + P @ V  (M=64 queries, N=128 head, K=64 keys)
        {
#pragma unroll
            for (int mt = 0; mt < 2; mt++) {
                float f0 = f_s[mQ + mt * 16 + g];
                float f8 = f_s[mQ + mt * 16 + g + 8];
#pragma unroll
                for (int ni = 0; ni < 4; ni++) {
                    oacc[mt][ni][0] *= f0; oacc[mt][ni][1] *= f0;
                    oacc[mt][ni][2] *= f8; oacc[mt][ni][3] *= f8;
                }
            }
#pragma unroll 4
            for (int k0 = 0; k0 < 8; k0++) {
                const int k = k0 * 8;
                uint32_t a[2][4], bf[4][2];
#pragma unroll
                for (int mt = 0; mt < 2; mt++) {
                    int r0 = mQ + mt * 16 + g;
                    a[mt][0] = __float_as_uint(S[r0 * ASS + k + tq]);
                    a[mt][1] = __float_as_uint(S[(r0 + 8) * ASS + k + tq]);
                    a[mt][2] = __float_as_uint(S[r0 * ASS + k + tq + 4]);
                    a[mt][3] = __float_as_uint(S[(r0 + 8) * ASS + k + tq + 4]);
                }
#pragma unroll
                for (int ni = 0; ni < 4; ni++) {
                    int ch = nH + ni * 8 + g;
                    bf[ni][0] = kvs[(k + tq) * AQ + ch];
                    bf[ni][1] = kvs[(k + tq + 4) * AQ + ch];
                }
#pragma unroll
                for (int mt = 0; mt < 2; mt++)
#pragma unroll
                    for (int ni = 0; ni < 4; ni++)
                        mma_tf32(oacc[mt][ni], a[mt], bf[ni]);
            }
        }
    }

    // ---- epilogue: normalize by 1/l, store
#pragma unroll
    for (int mt = 0; mt < 2; mt++) {
        int r0 = mQ + mt * 16 + g;
        float i0 = 1.f / l_s[r0];
        float i8 = 1.f / l_s[r0 + 8];
#pragma unroll
        for (int ni = 0; ni < 4; ni++) {
            int c = nH + ni * 8 + 2 * tq;
            float2 lo = {oacc[mt][ni][0] * i0, oacc[mt][ni][1] * i0};
            float2 hi = {oacc[mt][ni][2] * i8, oacc[mt][ni][3] * i8};
            *(float2*)&dout[((size_t)b * TT + qr0 + r0) * HH + c] = lo;
            *(float2*)&dout[((size_t)b * TT + qr0 + r0 + 8) * HH + c] = hi;
        }
    }
}

// ---------------------------------------------------------------------------
extern "C" void kernel_launch(void* const* d_in, const int* in_sizes, int n_in,
                              void* d_out, int out_size)
{
    const float* x  = (const float*)d_in[0];
    const float* Wk = (const float*)d_in[1];
    const float* Wq = (const float*)d_in[2];
    const float* Wv = (const float*)d_in[3];
    float* out = (float*)d_out;

    cudaFuncSetAttribute(proj_kernel, cudaFuncAttributeMaxDynamicSharedMemorySize, PROJ_SMEM);
    cudaFuncSetAttribute(attn_kernel, cudaFuncAttributeMaxDynamicSharedMemorySize, ATTN_SMEM);

    proj_kernel<<<dim3((BB * TT) / 64, 3), 256, PROJ_SMEM>>>(x, Wk, Wq, Wv, out);
    attn_kernel<<<dim3(4, BB), 256, ATTN_SMEM>>>(out);
}